// round 11
// baseline (speedup 1.0000x reference)
#include <cuda_runtime.h>
#include <cuda_fp16.h>
#include <mma.h>
#include <math.h>
#include <stdint.h>

using namespace nvcuda;

// ---------------- problem constants ----------------
#define BB 4096
#define KK 32
#define SD 512          // STATE_DIM
#define ED 128          // ENC_DIM
#define HH 128          // H
#define G4 512          // 4*H
#define RR (BB*KK)      // 131072 rows
#define MLPIN 1024
#define H1 1024
#define H2 512
#define NRB (RR/128)    // 1024 GEMM row-blocks

// ---------------- device scratch ----------------
__device__ float  g_XPf[(size_t)RR*G4];    // x_proj forward (fp32)
__device__ float  g_XPr[(size_t)RR*G4];    // x_proj reverse (fp32)
__device__ __half g_Xh [(size_t)RR*MLPIN]; // MLP input fp16 (S|Of|Or|V|A)
__device__ float  g_Y1 [(size_t)RR*H1];    // pre-BN layer1
__device__ __half g_H1h[(size_t)RR*H1];    // post-BN+ReLU layer1 (fp16)
__device__ float  g_Y2 [(size_t)RR*H2];
__device__ float  g_bnsum[NRB*H1], g_bnsq[NRB*H1];
__device__ float  g_mean[H1], g_istd[H1];
__device__ float  g_regpart[18*16];
__device__ __half g_W1h[(size_t)H1*MLPIN];
__device__ __half g_W2h[(size_t)H2*H1];
__device__ __half g_wihfh[G4*ED], g_wihrh[G4*ED];

// ---------------- cp.async helpers ----------------
__device__ __forceinline__ void cp16(void* sm, const void* g) {
    uint32_t a = (uint32_t)__cvta_generic_to_shared(sm);
    asm volatile("cp.async.ca.shared.global [%0], [%1], 16;\n" :: "r"(a), "l"(g));
}
__device__ __forceinline__ void cp_commit() { asm volatile("cp.async.commit_group;\n"); }
template<int N> __device__ __forceinline__ void cp_wait() {
    asm volatile("cp.async.wait_group %0;\n" :: "n"(N));
}

// ---------------- fp32 -> fp16 convert ----------------
__global__ void tohalf(const float* __restrict__ src, __half* __restrict__ dst, int n) {
    int i = blockIdx.x * blockDim.x + threadIdx.x;
    if (i < n) dst[i] = __float2half(src[i]);
}

// ---------------- fp16 wmma GEMM, 3-stage cp.async, 64x64 warp tiles ----------------
// C[M,N] = A[M,K] * B[N,K]^T, fp32 accumulate, no bias.
// 128 threads (4 warps); CTA tile 128x128; warp tile 64x64.
// smem stride 40 halves (80B): conflict-free ldmatrix, 16B-aligned.
#define HBM_ 128
#define HBN_ 128
#define HBK_ 32
#define HLD_ 40
#define STG_ 3
#define HTILE (HBM_ * HLD_)
#define HG_SMEM (STG_ * 2 * HTILE * 2)   // 61440 bytes

template<int DO_BN>
__global__ __launch_bounds__(128, 2)
void hgemm_nt(const __half* __restrict__ A, int lda,
              const __half* __restrict__ B, int ldb,
              float* __restrict__ C, int N, int K) {
    extern __shared__ __align__(16) char dynsm[];
    __half* As = (__half*)dynsm;
    __half* Bs = As + STG_ * HTILE;

    const int tid   = threadIdx.x;
    const int brow  = blockIdx.y * HBM_;
    const int bcol  = blockIdx.x * HBN_;
    const int warpid = tid >> 5;
    const int wm = warpid & 1;   // 64-row slab
    const int wn = warpid >> 1;  // 64-col slab

    wmma::fragment<wmma::accumulator, 16, 16, 16, float> c[4][4];
    #pragma unroll
    for (int i = 0; i < 4; i++)
        #pragma unroll
        for (int j = 0; j < 4; j++) wmma::fill_fragment(c[i][j], 0.0f);

    // loads: 128 threads; thread owns one row, 4x16B per tile
    auto issue = [&](int st, int k0) {
        const __half* Ag = &A[(size_t)(brow + tid) * lda + k0];
        const __half* Bg = &B[(size_t)(bcol + tid) * ldb + k0];
        __half* Asm = &As[st * HTILE + tid * HLD_];
        __half* Bsm = &Bs[st * HTILE + tid * HLD_];
        #pragma unroll
        for (int i = 0; i < 4; i++) {
            cp16(Asm + i * 8, Ag + i * 8);
            cp16(Bsm + i * 8, Bg + i * 8);
        }
        cp_commit();
    };

    const int nt = K / HBK_;   // >= 4 for all our shapes
    issue(0, 0); issue(1, HBK_); issue(2, 2 * HBK_);

    for (int i = 0; i < nt; i++) {
        const int st = i % STG_;
        if (i <= nt - STG_)      cp_wait<STG_-1>();
        else if (i == nt - 2)    cp_wait<1>();
        else                     cp_wait<0>();
        __syncthreads();

        #pragma unroll
        for (int kk = 0; kk < HBK_; kk += 16) {
            wmma::fragment<wmma::matrix_a, 16, 16, 16, __half, wmma::row_major> af[4];
            #pragma unroll
            for (int ii = 0; ii < 4; ii++)
                wmma::load_matrix_sync(af[ii], &As[st * HTILE + (wm * 64 + ii * 16) * HLD_ + kk], HLD_);
            #pragma unroll
            for (int j = 0; j < 4; j++) {
                wmma::fragment<wmma::matrix_b, 16, 16, 16, __half, wmma::col_major> bf;
                wmma::load_matrix_sync(bf, &Bs[st * HTILE + (wn * 64 + j * 16) * HLD_ + kk], HLD_);
                #pragma unroll
                for (int ii = 0; ii < 4; ii++)
                    wmma::mma_sync(c[ii][j], af[ii], bf, c[ii][j]);
            }
        }
        __syncthreads();
        if (i + STG_ < nt) issue(st, (i + STG_) * HBK_);
    }

    #pragma unroll
    for (int i = 0; i < 4; i++)
        #pragma unroll
        for (int j = 0; j < 4; j++)
            wmma::store_matrix_sync(
                &C[(size_t)(brow + wm * 64 + i * 16) * N + bcol + wn * 64 + j * 16],
                c[i][j], N, wmma::mem_row_major);

    if (DO_BN) {
        __syncthreads();   // make C-tile stores visible / complete ordering within CTA
        const int col = tid;   // 128 cols
        const float* cp = C + (size_t)brow * N + bcol + col;
        float s = 0.f, s2 = 0.f;
        #pragma unroll 8
        for (int r = 0; r < 128; r++) {
            float v = cp[(size_t)r * N];
            s += v; s2 += v * v;
        }
        g_bnsum[(size_t)blockIdx.y * N + bcol + col] = s;
        g_bnsq [(size_t)blockIdx.y * N + bcol + col] = s2;
    }
}

// ---------------- persistent fused bidirectional LSTM ----------------
#define LROWS 32
#define LHLD  136
#define GLD   520
#define LSMEM_G     0
#define LSMEM_BIAS  (LSMEM_G + LROWS * GLD * 4)
#define LSMEM_WHH   (LSMEM_BIAS + G4 * 4)
#define LSMEM_H     (LSMEM_WHH + G4 * LHLD * 2)
#define LSMEM_TOTAL (LSMEM_H + LROWS * LHLD * 2)

__global__ __launch_bounds__(256, 1)
void lstm_fused(const float* __restrict__ whh_f, const float* __restrict__ whh_r,
                const float* __restrict__ bihf, const float* __restrict__ bhhf,
                const float* __restrict__ bihr, const float* __restrict__ bhhr) {
    extern __shared__ char smem[];
    float*  sG    = (float*)(smem + LSMEM_G);
    float*  sBias = (float*)(smem + LSMEM_BIAS);
    __half* sWhh  = (__half*)(smem + LSMEM_WHH);
    __half* sH    = (__half*)(smem + LSMEM_H);

    const int z  = blockIdx.y;
    const int b0 = blockIdx.x * LROWS;
    const int tid = threadIdx.x;
    const int warpid = tid >> 5;

    const float* Whh = z ? whh_r : whh_f;
    const float* XP  = z ? g_XPr : g_XPf;
    const float* bih = z ? bihr : bihf;
    const float* bhh = z ? bhhr : bhhf;
    const int colbase = z ? 640 : 512;

    for (int i = tid; i < G4 * HH; i += 256) {
        const int n = i >> 7, k = i & 127;
        sWhh[n * LHLD + k] = __float2half(Whh[i]);
    }
    for (int i = tid; i < G4; i += 256) sBias[i] = bih[i] + bhh[i];
    for (int i = tid; i < LROWS * LHLD; i += 256) sH[i] = __float2half(0.f);

    float creg[16];
    #pragma unroll
    for (int e = 0; e < 16; e++) creg[e] = 0.f;
    __syncthreads();

    for (int t = 0; t < KK; t++) {
        const int k = z ? (KK - 1 - t) : t;
        {
            wmma::fragment<wmma::accumulator, 16, 16, 16, float> acc[2][4];
            #pragma unroll
            for (int i = 0; i < 2; i++)
                #pragma unroll
                for (int j = 0; j < 4; j++) wmma::fill_fragment(acc[i][j], 0.0f);

            #pragma unroll
            for (int kk = 0; kk < HH; kk += 16) {
                wmma::fragment<wmma::matrix_a, 16, 16, 16, __half, wmma::row_major> a0, a1;
                wmma::load_matrix_sync(a0, &sH[0 * LHLD + kk], LHLD);
                wmma::load_matrix_sync(a1, &sH[16 * LHLD + kk], LHLD);
                #pragma unroll
                for (int j = 0; j < 4; j++) {
                    wmma::fragment<wmma::matrix_b, 16, 16, 16, __half, wmma::col_major> bfr;
                    wmma::load_matrix_sync(bfr, &sWhh[(warpid * 64 + j * 16) * LHLD + kk], LHLD);
                    wmma::mma_sync(acc[0][j], a0, bfr, acc[0][j]);
                    wmma::mma_sync(acc[1][j], a1, bfr, acc[1][j]);
                }
            }
            #pragma unroll
            for (int i = 0; i < 2; i++)
                #pragma unroll
                for (int j = 0; j < 4; j++)
                    wmma::store_matrix_sync(&sG[(i * 16) * GLD + warpid * 64 + j * 16],
                                            acc[i][j], GLD, wmma::mem_row_major);
        }
        __syncthreads();

        #pragma unroll
        for (int e = 0; e < 16; e++) {
            const int idx = tid + 256 * e;
            const int row = idx >> 7;
            const int j   = idx & 127;
            const size_t r = (size_t)(b0 + row) * KK + k;
            const float* xp = XP + r * G4;
            const float* gr = sG + row * GLD;

            const float zi = xp[j]       + gr[j]       + sBias[j];
            const float zf = xp[128 + j] + gr[128 + j] + sBias[128 + j];
            const float zg = xp[256 + j] + gr[256 + j] + sBias[256 + j];
            const float zo = xp[384 + j] + gr[384 + j] + sBias[384 + j];

            const float si = 1.f / (1.f + expf(-zi));
            const float sf = 1.f / (1.f + expf(-zf));
            const float so = 1.f / (1.f + expf(-zo));

            const float cn = sf * creg[e] + si * tanhf(zg);
            const float hn = so * tanhf(cn);
            creg[e] = cn;

            sH[row * LHLD + j] = __float2half(hn);
            g_Xh[r * MLPIN + colbase + j] = __float2half(hn);
        }
        __syncthreads();
    }
}

// ---------------- fill X (fp16) with state + V ----------------
__global__ void fill_X(const float* __restrict__ state, const float* __restrict__ action) {
    const int r = blockIdx.x;
    const int tid = threadIdx.x;     // 128
    const int b = r >> 5;
    __half* xrow = g_Xh + (size_t)r * MLPIN;
    const float* srow = state + (size_t)b * SD;
    #pragma unroll
    for (int c = tid; c < SD; c += 128) xrow[c] = __float2half(srow[c]);
    xrow[768 + tid] = __float2half(action[(size_t)r * ED + tid]);
}

// ---------------- self-attention, register-blocked ----------------
#define VLD 133
__global__ __launch_bounds__(128)
void attn_kernel(const float* __restrict__ V) {
    const int b = blockIdx.x;
    __shared__ float sV[32 * VLD];
    __shared__ float sS[32 * 33];
    const int tid = threadIdx.x;  // 128
    const float* Vb = V + (size_t)b * KK * ED;

    for (int i = tid; i < KK * ED; i += 128)
        sV[(i >> 7) * VLD + (i & 127)] = Vb[i];
    __syncthreads();

    {
        const int rp = tid >> 3;
        const int cq = tid & 7;
        float acc[2][4];
        #pragma unroll
        for (int i = 0; i < 2; i++)
            #pragma unroll
            for (int j = 0; j < 4; j++) acc[i][j] = 0.f;

        #pragma unroll 4
        for (int d = 0; d < ED; d++) {
            const float a0 = sV[(2 * rp)     * VLD + d];
            const float a1 = sV[(2 * rp + 1) * VLD + d];
            #pragma unroll
            for (int j = 0; j < 4; j++) {
                const float bv = sV[(4 * cq + j) * VLD + d];
                acc[0][j] += a0 * bv;
                acc[1][j] += a1 * bv;
            }
        }
        #pragma unroll
        for (int i = 0; i < 2; i++)
            #pragma unroll
            for (int j = 0; j < 4; j++)
                sS[(2 * rp + i) * 33 + 4 * cq + j] = acc[i][j];
    }
    __syncthreads();

    if (tid < KK) {
        float mx = -1e30f;
        for (int c = 0; c < KK; c++) mx = fmaxf(mx, sS[tid * 33 + c]);
        float sum = 0.f;
        for (int c = 0; c < KK; c++) { float e = expf(sS[tid * 33 + c] - mx); sS[tid * 33 + c] = e; sum += e; }
        float inv = 1.f / sum;
        for (int c = 0; c < KK; c++) sS[tid * 33 + c] *= inv;
    }
    __syncthreads();

    {
        float a[32];
        #pragma unroll
        for (int k = 0; k < 32; k++) a[k] = 0.f;
        #pragma unroll 4
        for (int l = 0; l < 32; l++) {
            const float vl = sV[l * VLD + tid];
            #pragma unroll
            for (int k = 0; k < 32; k++) a[k] += sS[k * 33 + l] * vl;
        }
        #pragma unroll
        for (int k = 0; k < 32; k++) {
            const size_t r = (size_t)b * KK + k;
            g_Xh[r * MLPIN + 896 + tid] = __float2half(a[k]);
        }
    }
}

// ---------------- BN finalize over 1024 row-block partials ----------------
__global__ void bn_finalize(int cols) {
    const int c = blockIdx.x * 128 + threadIdx.x;
    float s = 0.f, s2 = 0.f;
    for (int rb = 0; rb < NRB; rb++) {
        s  += g_bnsum[(size_t)rb * cols + c];
        s2 += g_bnsq [(size_t)rb * cols + c];
    }
    const float mu  = s  / (float)RR;
    const float var = s2 / (float)RR - mu * mu;
    g_mean[c] = mu;
    g_istd[c] = rsqrtf(var + 1e-5f);
}

// ---------------- layer-1 BN+ReLU -> fp16 ----------------
__global__ void bn_apply_relu_h(const float* __restrict__ Y, __half* __restrict__ out,
                                const float* __restrict__ gamma,
                                const float* __restrict__ beta, int cols) {
    const size_t total = (size_t)RR * cols;
    const int mask = cols - 1;
    size_t i = (size_t)blockIdx.x * blockDim.x + threadIdx.x;
    const size_t stride = (size_t)gridDim.x * blockDim.x;
    for (; i < total; i += stride) {
        const int c = (int)(i & mask);
        float v = (Y[i] - g_mean[c]) * g_istd[c] * gamma[c] + beta[c];
        out[i] = __float2half(v > 0.f ? v : 0.f);
    }
}

// ---------------- final layer with fused layer-2 BN+ReLU ----------------
__global__ __launch_bounds__(256)
void final_q(const float* __restrict__ W3, const float* __restrict__ b3,
             const float* __restrict__ g2, const float* __restrict__ be2,
             float* __restrict__ out) {
    __shared__ float sw[H2], smu[H2], sis[H2], sg[H2], sb[H2];
    const int tid = threadIdx.x;
    for (int i = tid; i < H2; i += 256) {
        sw[i] = W3[i]; smu[i] = g_mean[i]; sis[i] = g_istd[i];
        sg[i] = g2[i]; sb[i] = be2[i];
    }
    __syncthreads();

    const int warp = tid >> 5, lane = tid & 31;
    const size_t row = (size_t)blockIdx.x * 8 + warp;
    const float* y = g_Y2 + row * H2;
    float s = 0.f;
    #pragma unroll
    for (int i = 0; i < H2 / 32; i++) {
        const int c = i * 32 + lane;
        float v = (y[c] - smu[c]) * sis[c] * sg[c] + sb[c];
        v = fmaxf(v, 0.f);
        s += v * sw[c];
    }
    #pragma unroll
    for (int o = 16; o; o >>= 1) s += __shfl_xor_sync(0xffffffffu, s, o);
    if (lane == 0) out[row] = s + b3[0];
}

// ---------------- regularizer ----------------
struct RegArgs { const float* p[18]; int n[18]; };

__global__ void reg_partial(RegArgs ra) {
    const int pi = blockIdx.x;
    const int ch = blockIdx.y;
    __shared__ float red[256];
    const float* p = ra.p[pi];
    const int n = ra.n[pi];
    const int per = (n + 15) / 16;
    const int lo = ch * per;
    const int hi = min(n, lo + per);
    float s = 0.f;
    for (int i = lo + threadIdx.x; i < hi; i += 256) { float v = p[i]; s += v * v; }
    red[threadIdx.x] = s;
    __syncthreads();
    for (int o = 128; o; o >>= 1) {
        if (threadIdx.x < o) red[threadIdx.x] += red[threadIdx.x + o];
        __syncthreads();
    }
    if (threadIdx.x == 0) g_regpart[pi * 16 + ch] = red[0] / (float)n;
}

__global__ void reg_final(float* out, int out_size) {
    if (threadIdx.x == 0 && blockIdx.x == 0) {
        float s = 0.f;
        for (int i = 0; i < 18 * 16; i++) s += g_regpart[i];
        if (out_size > RR) out[RR] = s;
    }
}

// ---------------- launch ----------------
extern "C" void kernel_launch(void* const* d_in, const int* in_sizes, int n_in,
                              void* d_out, int out_size) {
    const float* state  = (const float*)d_in[0];
    const float* action = (const float*)d_in[1];
    const float* w_ih_f = (const float*)d_in[2];
    const float* w_hh_f = (const float*)d_in[3];
    const float* b_ih_f = (const float*)d_in[4];
    const float* b_hh_f = (const float*)d_in[5];
    const float* w_ih_r = (const float*)d_in[6];
    const float* w_hh_r = (const float*)d_in[7];
    const float* b_ih_r = (const float*)d_in[8];
    const float* b_hh_r = (const float*)d_in[9];
    const float* W1 = (const float*)d_in[10];
    const float* g1 = (const float*)d_in[12];
    const float* be1 = (const float*)d_in[13];
    const float* W2 = (const float*)d_in[14];
    const float* g2 = (const float*)d_in[16];
    const float* be2 = (const float*)d_in[17];
    const float* W3 = (const float*)d_in[18];
    const float* b3 = (const float*)d_in[19];
    float* out = (float*)d_out;

    float *pXPf, *pXPr, *pY1, *pY2;
    __half *pXh, *pH1h, *pW1h, *pW2h, *pwfh, *pwrh;
    cudaGetSymbolAddress((void**)&pXPf, g_XPf);
    cudaGetSymbolAddress((void**)&pXPr, g_XPr);
    cudaGetSymbolAddress((void**)&pXh,  g_Xh);
    cudaGetSymbolAddress((void**)&pY1,  g_Y1);
    cudaGetSymbolAddress((void**)&pH1h, g_H1h);
    cudaGetSymbolAddress((void**)&pY2,  g_Y2);
    cudaGetSymbolAddress((void**)&pW1h, g_W1h);
    cudaGetSymbolAddress((void**)&pW2h, g_W2h);
    cudaGetSymbolAddress((void**)&pwfh, g_wihfh);
    cudaGetSymbolAddress((void**)&pwrh, g_wihrh);

    cudaFuncSetAttribute(lstm_fused, cudaFuncAttributeMaxDynamicSharedMemorySize, LSMEM_TOTAL);
    cudaFuncSetAttribute(hgemm_nt<0>, cudaFuncAttributeMaxDynamicSharedMemorySize, HG_SMEM);
    cudaFuncSetAttribute(hgemm_nt<1>, cudaFuncAttributeMaxDynamicSharedMemorySize, HG_SMEM);

    // 0. weight conversions (tiny)
    tohalf<<<(H1*MLPIN + 255)/256, 256>>>(W1, pW1h, H1*MLPIN);
    tohalf<<<(H2*H1   + 255)/256, 256>>>(W2, pW2h, H2*H1);
    tohalf<<<(G4*ED   + 255)/256, 256>>>(w_ih_f, pwfh, G4*ED);
    tohalf<<<(G4*ED   + 255)/256, 256>>>(w_ih_r, pwrh, G4*ED);

    // 1. fill X fp16: state + V columns
    fill_X<<<RR, 128>>>(state, action);

    // 2. attention -> Xh[:,896:1024]
    attn_kernel<<<BB, 128>>>(action);

    // 3. x_proj both directions
    hgemm_nt<0><<<dim3(G4/HBN_, RR/HBM_), 128, HG_SMEM>>>(pXh + 768, MLPIN, pwfh, ED, pXPf, G4, ED);
    hgemm_nt<0><<<dim3(G4/HBN_, RR/HBM_), 128, HG_SMEM>>>(pXh + 768, MLPIN, pwrh, ED, pXPr, G4, ED);

    // 4. fused persistent LSTM (both directions)
    lstm_fused<<<dim3(BB/LROWS, 2), 256, LSMEM_TOTAL>>>(w_hh_f, w_hh_r,
                                                        b_ih_f, b_hh_f, b_ih_r, b_hh_r);

    // 5. MLP layer 1 + fused BN stats (b1 dropped: BN shift-invariant)
    hgemm_nt<1><<<dim3(H1/HBN_, RR/HBM_), 128, HG_SMEM>>>(pXh, MLPIN, pW1h, MLPIN, pY1, H1, MLPIN);
    bn_finalize<<<H1/128, 128>>>(H1);
    bn_apply_relu_h<<<2048, 256>>>(pY1, pH1h, g1, be1, H1);

    // 6. MLP layer 2 + fused BN stats (b2 dropped)
    hgemm_nt<1><<<dim3(H2/HBN_, RR/HBM_), 128, HG_SMEM>>>(pH1h, H1, pW2h, H1, pY2, H2, H1);
    bn_finalize<<<H2/128, 128>>>(H2);

    // 7. final layer with fused layer-2 BN+ReLU
    final_q<<<RR/8, 256>>>(W3, b3, g2, be2, out);

    // 8. regularizer
    {
        RegArgs ra;
        for (int i = 0; i < 18; i++) {
            ra.p[i] = (const float*)d_in[2 + i];
            ra.n[i] = in_sizes[2 + i];
        }
        reg_partial<<<dim3(18, 16), 256>>>(ra);
        reg_final<<<1, 32>>>(out, out_size);
    }
}

// round 13
// speedup vs baseline: 1.2547x; 1.2547x over previous
#include <cuda_runtime.h>
#include <cuda_fp16.h>
#include <mma.h>
#include <math.h>
#include <stdint.h>

using namespace nvcuda;

// ---------------- problem constants ----------------
#define BB 4096
#define KK 32
#define SD 512          // STATE_DIM
#define ED 128          // ENC_DIM
#define HH 128          // H
#define G4 512          // 4*H
#define RR (BB*KK)      // 131072 rows
#define MLPIN 1024
#define H1 1024
#define H2 512
#define NRB (RR/128)    // 1024 GEMM row-blocks

// ---------------- device scratch ----------------
__device__ float  g_XPf[(size_t)RR*G4];    // x_proj forward (fp32)
__device__ float  g_XPr[(size_t)RR*G4];    // x_proj reverse (fp32)
__device__ __half g_Xh [(size_t)RR*MLPIN]; // MLP input fp16 (S|Of|Or|V|A)
__device__ float  g_Y1 [(size_t)RR*H1];    // pre-BN layer1
__device__ __half g_H1h[(size_t)RR*H1];    // post-BN+ReLU layer1 (fp16)
__device__ float  g_Y2 [(size_t)RR*H2];
__device__ float  g_bnsum[NRB*H1], g_bnsq[NRB*H1];
__device__ float  g_mean[H1], g_istd[H1];
__device__ float  g_regpart[18*16];
__device__ __half g_W1h[(size_t)H1*MLPIN];
__device__ __half g_W2h[(size_t)H2*H1];
__device__ __half g_wihfh[G4*ED], g_wihrh[G4*ED];

// ---------------- cp.async helpers ----------------
__device__ __forceinline__ void cp16(void* sm, const void* g) {
    uint32_t a = (uint32_t)__cvta_generic_to_shared(sm);
    asm volatile("cp.async.ca.shared.global [%0], [%1], 16;\n" :: "r"(a), "l"(g));
}
__device__ __forceinline__ void cp_commit() { asm volatile("cp.async.commit_group;\n"); }
template<int N> __device__ __forceinline__ void cp_wait() {
    asm volatile("cp.async.wait_group %0;\n" :: "n"(N));
}

// ---------------- fp32 -> fp16 convert ----------------
__global__ void tohalf(const float* __restrict__ src, __half* __restrict__ dst, int n) {
    int i = blockIdx.x * blockDim.x + threadIdx.x;
    if (i < n) dst[i] = __float2half(src[i]);
}

// ---------------- fp16 wmma GEMM, 3-stage cp.async (round-8 shape, HLD_=40) ----
// C[M,N] = A[M,K] * B[N,K]^T, fp32 accumulate, no bias.
// 256 threads (8 warps); CTA tile 128x128; warp tile 64x32.
// smem stride 40 halves (80B): conflict-free ldmatrix (r*20 mod 32 -> 8 distinct banks).
#define HBM_ 128
#define HBN_ 128
#define HBK_ 32
#define HLD_ 40
#define STG_ 3
#define HTILE (HBM_ * HLD_)
#define HG_SMEM (STG_ * 2 * HTILE * 2)   // 61440 bytes

template<int DO_BN>
__global__ __launch_bounds__(256, 2)
void hgemm_nt(const __half* __restrict__ A, int lda,
              const __half* __restrict__ B, int ldb,
              float* __restrict__ C, int N, int K) {
    extern __shared__ __align__(16) char dynsm[];
    __half* As = (__half*)dynsm;
    __half* Bs = As + STG_ * HTILE;

    const int tid   = threadIdx.x;
    const int brow  = blockIdx.y * HBM_;
    const int bcol  = blockIdx.x * HBN_;
    const int warpid = tid >> 5;
    const int wm = warpid & 1;   // 64-row slab
    const int wn = warpid >> 1;  // 32-col slab

    wmma::fragment<wmma::accumulator, 16, 16, 16, float> c[4][2];
    #pragma unroll
    for (int i = 0; i < 4; i++)
        #pragma unroll
        for (int j = 0; j < 2; j++) wmma::fill_fragment(c[i][j], 0.0f);

    const int lr = tid >> 2;          // 0..63
    const int lc = (tid & 3) * 8;     // halves

    auto issue = [&](int st, int k0) {
        #pragma unroll
        for (int s = 0; s < 2; s++) {
            const int r = lr + s * 64;
            cp16(&As[st * HTILE + r * HLD_ + lc], &A[(size_t)(brow + r) * lda + k0 + lc]);
            cp16(&Bs[st * HTILE + r * HLD_ + lc], &B[(size_t)(bcol + r) * ldb + k0 + lc]);
        }
        cp_commit();
    };

    const int nt = K / HBK_;   // >= 4 for all our shapes
    issue(0, 0); issue(1, HBK_); issue(2, 2 * HBK_);

    for (int i = 0; i < nt; i++) {
        const int st = i % STG_;
        if (i <= nt - STG_)      cp_wait<STG_-1>();
        else if (i == nt - 2)    cp_wait<1>();
        else                     cp_wait<0>();
        __syncthreads();

        #pragma unroll
        for (int kk = 0; kk < HBK_; kk += 16) {
            wmma::fragment<wmma::matrix_a, 16, 16, 16, __half, wmma::row_major> af[4];
            wmma::fragment<wmma::matrix_b, 16, 16, 16, __half, wmma::col_major> bf[2];
            #pragma unroll
            for (int ii = 0; ii < 4; ii++)
                wmma::load_matrix_sync(af[ii], &As[st * HTILE + (wm * 64 + ii * 16) * HLD_ + kk], HLD_);
            #pragma unroll
            for (int j = 0; j < 2; j++)
                wmma::load_matrix_sync(bf[j], &Bs[st * HTILE + (wn * 32 + j * 16) * HLD_ + kk], HLD_);
            #pragma unroll
            for (int ii = 0; ii < 4; ii++)
                #pragma unroll
                for (int j = 0; j < 2; j++)
                    wmma::mma_sync(c[ii][j], af[ii], bf[j], c[ii][j]);
        }
        __syncthreads();
        if (i + STG_ < nt) issue(st, (i + STG_) * HBK_);
    }

    #pragma unroll
    for (int i = 0; i < 4; i++)
        #pragma unroll
        for (int j = 0; j < 2; j++)
            wmma::store_matrix_sync(
                &C[(size_t)(brow + wm * 64 + i * 16) * N + bcol + wn * 32 + j * 16],
                c[i][j], N, wmma::mem_row_major);

    if (DO_BN) {
        __syncthreads();
        __shared__ float redS[256], redQ[256];
        const int col = tid & 127;
        const int hh  = tid >> 7;          // 0..1 -> 64-row halves
        const float* cp = C + (size_t)(brow + hh * 64) * N + bcol + col;
        float s = 0.f, s2 = 0.f;
        #pragma unroll 8
        for (int r = 0; r < 64; r++) {
            float v = cp[(size_t)r * N];
            s += v; s2 += v * v;
        }
        redS[tid] = s; redQ[tid] = s2;
        __syncthreads();
        if (tid < 128) {
            g_bnsum[(size_t)blockIdx.y * N + bcol + tid] = redS[tid] + redS[tid + 128];
            g_bnsq [(size_t)blockIdx.y * N + bcol + tid] = redQ[tid] + redQ[tid + 128];
        }
    }
}

// ---------------- persistent fused bidirectional LSTM ----------------
#define LROWS 32
#define LHLD  136
#define GLD   520
#define LSMEM_G     0
#define LSMEM_BIAS  (LSMEM_G + LROWS * GLD * 4)
#define LSMEM_WHH   (LSMEM_BIAS + G4 * 4)
#define LSMEM_H     (LSMEM_WHH + G4 * LHLD * 2)
#define LSMEM_TOTAL (LSMEM_H + LROWS * LHLD * 2)

__global__ __launch_bounds__(256, 1)
void lstm_fused(const float* __restrict__ whh_f, const float* __restrict__ whh_r,
                const float* __restrict__ bihf, const float* __restrict__ bhhf,
                const float* __restrict__ bihr, const float* __restrict__ bhhr) {
    extern __shared__ char smem[];
    float*  sG    = (float*)(smem + LSMEM_G);
    float*  sBias = (float*)(smem + LSMEM_BIAS);
    __half* sWhh  = (__half*)(smem + LSMEM_WHH);
    __half* sH    = (__half*)(smem + LSMEM_H);

    const int z  = blockIdx.y;
    const int b0 = blockIdx.x * LROWS;
    const int tid = threadIdx.x;
    const int warpid = tid >> 5;

    const float* Whh = z ? whh_r : whh_f;
    const float* XP  = z ? g_XPr : g_XPf;
    const float* bih = z ? bihr : bihf;
    const float* bhh = z ? bhhr : bhhf;
    const int colbase = z ? 640 : 512;

    for (int i = tid; i < G4 * HH; i += 256) {
        const int n = i >> 7, k = i & 127;
        sWhh[n * LHLD + k] = __float2half(Whh[i]);
    }
    for (int i = tid; i < G4; i += 256) sBias[i] = bih[i] + bhh[i];
    for (int i = tid; i < LROWS * LHLD; i += 256) sH[i] = __float2half(0.f);

    float creg[16];
    #pragma unroll
    for (int e = 0; e < 16; e++) creg[e] = 0.f;
    __syncthreads();

    for (int t = 0; t < KK; t++) {
        const int k = z ? (KK - 1 - t) : t;
        {
            wmma::fragment<wmma::accumulator, 16, 16, 16, float> acc[2][4];
            #pragma unroll
            for (int i = 0; i < 2; i++)
                #pragma unroll
                for (int j = 0; j < 4; j++) wmma::fill_fragment(acc[i][j], 0.0f);

            #pragma unroll
            for (int kk = 0; kk < HH; kk += 16) {
                wmma::fragment<wmma::matrix_a, 16, 16, 16, __half, wmma::row_major> a0, a1;
                wmma::load_matrix_sync(a0, &sH[0 * LHLD + kk], LHLD);
                wmma::load_matrix_sync(a1, &sH[16 * LHLD + kk], LHLD);
                #pragma unroll
                for (int j = 0; j < 4; j++) {
                    wmma::fragment<wmma::matrix_b, 16, 16, 16, __half, wmma::col_major> bfr;
                    wmma::load_matrix_sync(bfr, &sWhh[(warpid * 64 + j * 16) * LHLD + kk], LHLD);
                    wmma::mma_sync(acc[0][j], a0, bfr, acc[0][j]);
                    wmma::mma_sync(acc[1][j], a1, bfr, acc[1][j]);
                }
            }
            #pragma unroll
            for (int i = 0; i < 2; i++)
                #pragma unroll
                for (int j = 0; j < 4; j++)
                    wmma::store_matrix_sync(&sG[(i * 16) * GLD + warpid * 64 + j * 16],
                                            acc[i][j], GLD, wmma::mem_row_major);
        }
        __syncthreads();

        #pragma unroll
        for (int e = 0; e < 16; e++) {
            const int idx = tid + 256 * e;
            const int row = idx >> 7;
            const int j   = idx & 127;
            const size_t r = (size_t)(b0 + row) * KK + k;
            const float* xp = XP + r * G4;
            const float* gr = sG + row * GLD;

            const float zi = xp[j]       + gr[j]       + sBias[j];
            const float zf = xp[128 + j] + gr[128 + j] + sBias[128 + j];
            const float zg = xp[256 + j] + gr[256 + j] + sBias[256 + j];
            const float zo = xp[384 + j] + gr[384 + j] + sBias[384 + j];

            const float si = 1.f / (1.f + expf(-zi));
            const float sf = 1.f / (1.f + expf(-zf));
            const float so = 1.f / (1.f + expf(-zo));

            const float cn = sf * creg[e] + si * tanhf(zg);
            const float hn = so * tanhf(cn);
            creg[e] = cn;

            sH[row * LHLD + j] = __float2half(hn);
            g_Xh[r * MLPIN + colbase + j] = __float2half(hn);
        }
        __syncthreads();
    }
}

// ---------------- fill X (fp16) with state + V ----------------
__global__ void fill_X(const float* __restrict__ state, const float* __restrict__ action) {
    const int r = blockIdx.x;
    const int tid = threadIdx.x;     // 128
    const int b = r >> 5;
    __half* xrow = g_Xh + (size_t)r * MLPIN;
    const float* srow = state + (size_t)b * SD;
    #pragma unroll
    for (int c = tid; c < SD; c += 128) xrow[c] = __float2half(srow[c]);
    xrow[768 + tid] = __float2half(action[(size_t)r * ED + tid]);
}

// ---------------- self-attention, register-blocked ----------------
#define VLD 133
__global__ __launch_bounds__(128)
void attn_kernel(const float* __restrict__ V) {
    const int b = blockIdx.x;
    __shared__ float sV[32 * VLD];
    __shared__ float sS[32 * 33];
    const int tid = threadIdx.x;  // 128
    const float* Vb = V + (size_t)b * KK * ED;

    for (int i = tid; i < KK * ED; i += 128)
        sV[(i >> 7) * VLD + (i & 127)] = Vb[i];
    __syncthreads();

    {
        const int rp = tid >> 3;
        const int cq = tid & 7;
        float acc[2][4];
        #pragma unroll
        for (int i = 0; i < 2; i++)
            #pragma unroll
            for (int j = 0; j < 4; j++) acc[i][j] = 0.f;

        #pragma unroll 4
        for (int d = 0; d < ED; d++) {
            const float a0 = sV[(2 * rp)     * VLD + d];
            const float a1 = sV[(2 * rp + 1) * VLD + d];
            #pragma unroll
            for (int j = 0; j < 4; j++) {
                const float bv = sV[(4 * cq + j) * VLD + d];
                acc[0][j] += a0 * bv;
                acc[1][j] += a1 * bv;
            }
        }
        #pragma unroll
        for (int i = 0; i < 2; i++)
            #pragma unroll
            for (int j = 0; j < 4; j++)
                sS[(2 * rp + i) * 33 + 4 * cq + j] = acc[i][j];
    }
    __syncthreads();

    if (tid < KK) {
        float mx = -1e30f;
        for (int c = 0; c < KK; c++) mx = fmaxf(mx, sS[tid * 33 + c]);
        float sum = 0.f;
        for (int c = 0; c < KK; c++) { float e = expf(sS[tid * 33 + c] - mx); sS[tid * 33 + c] = e; sum += e; }
        float inv = 1.f / sum;
        for (int c = 0; c < KK; c++) sS[tid * 33 + c] *= inv;
    }
    __syncthreads();

    {
        float a[32];
        #pragma unroll
        for (int k = 0; k < 32; k++) a[k] = 0.f;
        #pragma unroll 4
        for (int l = 0; l < 32; l++) {
            const float vl = sV[l * VLD + tid];
            #pragma unroll
            for (int k = 0; k < 32; k++) a[k] += sS[k * 33 + l] * vl;
        }
        #pragma unroll
        for (int k = 0; k < 32; k++) {
            const size_t r = (size_t)b * KK + k;
            g_Xh[r * MLPIN + 896 + tid] = __float2half(a[k]);
        }
    }
}

// ---------------- BN finalize over 1024 row-block partials ----------------
__global__ void bn_finalize(int cols) {
    const int c = blockIdx.x * 128 + threadIdx.x;
    float s = 0.f, s2 = 0.f;
    for (int rb = 0; rb < NRB; rb++) {
        s  += g_bnsum[(size_t)rb * cols + c];
        s2 += g_bnsq [(size_t)rb * cols + c];
    }
    const float mu  = s  / (float)RR;
    const float var = s2 / (float)RR - mu * mu;
    g_mean[c] = mu;
    g_istd[c] = rsqrtf(var + 1e-5f);
}

// ---------------- layer-1 BN+ReLU -> fp16 ----------------
__global__ void bn_apply_relu_h(const float* __restrict__ Y, __half* __restrict__ out,
                                const float* __restrict__ gamma,
                                const float* __restrict__ beta, int cols) {
    const size_t total = (size_t)RR * cols;
    const int mask = cols - 1;
    size_t i = (size_t)blockIdx.x * blockDim.x + threadIdx.x;
    const size_t stride = (size_t)gridDim.x * blockDim.x;
    for (; i < total; i += stride) {
        const int c = (int)(i & mask);
        float v = (Y[i] - g_mean[c]) * g_istd[c] * gamma[c] + beta[c];
        out[i] = __float2half(v > 0.f ? v : 0.f);
    }
}

// ---------------- final layer with fused layer-2 BN+ReLU ----------------
__global__ __launch_bounds__(256)
void final_q(const float* __restrict__ W3, const float* __restrict__ b3,
             const float* __restrict__ g2, const float* __restrict__ be2,
             float* __restrict__ out) {
    __shared__ float sw[H2], smu[H2], sis[H2], sg[H2], sb[H2];
    const int tid = threadIdx.x;
    for (int i = tid; i < H2; i += 256) {
        sw[i] = W3[i]; smu[i] = g_mean[i]; sis[i] = g_istd[i];
        sg[i] = g2[i]; sb[i] = be2[i];
    }
    __syncthreads();

    const int warp = tid >> 5, lane = tid & 31;
    const size_t row = (size_t)blockIdx.x * 8 + warp;
    const float* y = g_Y2 + row * H2;
    float s = 0.f;
    #pragma unroll
    for (int i = 0; i < H2 / 32; i++) {
        const int c = i * 32 + lane;
        float v = (y[c] - smu[c]) * sis[c] * sg[c] + sb[c];
        v = fmaxf(v, 0.f);
        s += v * sw[c];
    }
    #pragma unroll
    for (int o = 16; o; o >>= 1) s += __shfl_xor_sync(0xffffffffu, s, o);
    if (lane == 0) out[row] = s + b3[0];
}

// ---------------- regularizer ----------------
struct RegArgs { const float* p[18]; int n[18]; };

__global__ void reg_partial(RegArgs ra) {
    const int pi = blockIdx.x;
    const int ch = blockIdx.y;
    __shared__ float red[256];
    const float* p = ra.p[pi];
    const int n = ra.n[pi];
    const int per = (n + 15) / 16;
    const int lo = ch * per;
    const int hi = min(n, lo + per);
    float s = 0.f;
    for (int i = lo + threadIdx.x; i < hi; i += 256) { float v = p[i]; s += v * v; }
    red[threadIdx.x] = s;
    __syncthreads();
    for (int o = 128; o; o >>= 1) {
        if (threadIdx.x < o) red[threadIdx.x] += red[threadIdx.x + o];
        __syncthreads();
    }
    if (threadIdx.x == 0) g_regpart[pi * 16 + ch] = red[0] / (float)n;
}

__global__ void reg_final(float* out, int out_size) {
    if (threadIdx.x == 0 && blockIdx.x == 0) {
        float s = 0.f;
        for (int i = 0; i < 18 * 16; i++) s += g_regpart[i];
        if (out_size > RR) out[RR] = s;
    }
}

// ---------------- launch ----------------
extern "C" void kernel_launch(void* const* d_in, const int* in_sizes, int n_in,
                              void* d_out, int out_size) {
    const float* state  = (const float*)d_in[0];
    const float* action = (const float*)d_in[1];
    const float* w_ih_f = (const float*)d_in[2];
    const float* w_hh_f = (const float*)d_in[3];
    const float* b_ih_f = (const float*)d_in[4];
    const float* b_hh_f = (const float*)d_in[5];
    const float* w_ih_r = (const float*)d_in[6];
    const float* w_hh_r = (const float*)d_in[7];
    const float* b_ih_r = (const float*)d_in[8];
    const float* b_hh_r = (const float*)d_in[9];
    const float* W1 = (const float*)d_in[10];
    const float* g1 = (const float*)d_in[12];
    const float* be1 = (const float*)d_in[13];
    const float* W2 = (const float*)d_in[14];
    const float* g2 = (const float*)d_in[16];
    const float* be2 = (const float*)d_in[17];
    const float* W3 = (const float*)d_in[18];
    const float* b3 = (const float*)d_in[19];
    float* out = (float*)d_out;

    float *pXPf, *pXPr, *pY1, *pY2;
    __half *pXh, *pH1h, *pW1h, *pW2h, *pwfh, *pwrh;
    cudaGetSymbolAddress((void**)&pXPf, g_XPf);
    cudaGetSymbolAddress((void**)&pXPr, g_XPr);
    cudaGetSymbolAddress((void**)&pXh,  g_Xh);
    cudaGetSymbolAddress((void**)&pY1,  g_Y1);
    cudaGetSymbolAddress((void**)&pH1h, g_H1h);
    cudaGetSymbolAddress((void**)&pY2,  g_Y2);
    cudaGetSymbolAddress((void**)&pW1h, g_W1h);
    cudaGetSymbolAddress((void**)&pW2h, g_W2h);
    cudaGetSymbolAddress((void**)&pwfh, g_wihfh);
    cudaGetSymbolAddress((void**)&pwrh, g_wihrh);

    cudaFuncSetAttribute(lstm_fused, cudaFuncAttributeMaxDynamicSharedMemorySize, LSMEM_TOTAL);
    cudaFuncSetAttribute(hgemm_nt<0>, cudaFuncAttributeMaxDynamicSharedMemorySize, HG_SMEM);
    cudaFuncSetAttribute(hgemm_nt<1>, cudaFuncAttributeMaxDynamicSharedMemorySize, HG_SMEM);

    // 0. weight conversions (tiny)
    tohalf<<<(H1*MLPIN + 255)/256, 256>>>(W1, pW1h, H1*MLPIN);
    tohalf<<<(H2*H1   + 255)/256, 256>>>(W2, pW2h, H2*H1);
    tohalf<<<(G4*ED   + 255)/256, 256>>>(w_ih_f, pwfh, G4*ED);
    tohalf<<<(G4*ED   + 255)/256, 256>>>(w_ih_r, pwrh, G4*ED);

    // 1. fill X fp16: state + V columns
    fill_X<<<RR, 128>>>(state, action);

    // 2. attention -> Xh[:,896:1024]
    attn_kernel<<<BB, 128>>>(action);

    // 3. x_proj both directions
    hgemm_nt<0><<<dim3(G4/HBN_, RR/HBM_), 256, HG_SMEM>>>(pXh + 768, MLPIN, pwfh, ED, pXPf, G4, ED);
    hgemm_nt<0><<<dim3(G4/HBN_, RR/HBM_), 256, HG_SMEM>>>(pXh + 768, MLPIN, pwrh, ED, pXPr, G4, ED);

    // 4. fused persistent LSTM (both directions)
    lstm_fused<<<dim3(BB/LROWS, 2), 256, LSMEM_TOTAL>>>(w_hh_f, w_hh_r,
                                                        b_ih_f, b_hh_f, b_ih_r, b_hh_r);

    // 5. MLP layer 1 + fused BN stats (b1 dropped: BN shift-invariant)
    hgemm_nt<1><<<dim3(H1/HBN_, RR/HBM_), 256, HG_SMEM>>>(pXh, MLPIN, pW1h, MLPIN, pY1, H1, MLPIN);
    bn_finalize<<<H1/128, 128>>>(H1);
    bn_apply_relu_h<<<2048, 256>>>(pY1, pH1h, g1, be1, H1);

    // 6. MLP layer 2 + fused BN stats (b2 dropped)
    hgemm_nt<1><<<dim3(H2/HBN_, RR/HBM_), 256, HG_SMEM>>>(pH1h, H1, pW2h, H1, pY2, H2, H1);
    bn_finalize<<<H2/128, 128>>>(H2);

    // 7. final layer with fused layer-2 BN+ReLU
    final_q<<<RR/8, 256>>>(W3, b3, g2, be2, out);

    // 8. regularizer
    {
        RegArgs ra;
        for (int i = 0; i < 18; i++) {
            ra.p[i] = (const float*)d_in[2 + i];
            ra.n[i] = in_sizes[2 + i];
        }
        reg_partial<<<dim3(18, 16), 256>>>(ra);
        reg_final<<<1, 32>>>(out, out_size);
    }
}

// round 14
// speedup vs baseline: 1.4167x; 1.1291x over previous
#include <cuda_runtime.h>
#include <cuda_fp16.h>
#include <mma.h>
#include <math.h>
#include <stdint.h>

using namespace nvcuda;

// ---------------- problem constants ----------------
#define BB 4096
#define KK 32
#define SD 512          // STATE_DIM
#define ED 128          // ENC_DIM
#define HH 128          // H
#define G4 512          // 4*H
#define RR (BB*KK)      // 131072 rows
#define MLPIN 1024
#define XV 512          // reduced MLP input cols (Of|Or|V|A)
#define H1 1024
#define H2 512
#define NRB (RR/128)    // 1024 GEMM row-blocks

// ---------------- device scratch ----------------
__device__ float  g_XPf[(size_t)RR*G4];    // x_proj forward (fp32)
__device__ float  g_XPr[(size_t)RR*G4];    // x_proj reverse (fp32)
__device__ __half g_Xv [(size_t)RR*XV];    // MLP input fp16 (Of|Or|V|A)
__device__ float  g_Y1s[(size_t)BB*H1];    // state @ W1s^T (per batch row)
__device__ float  g_Y1 [(size_t)RR*H1];    // pre-BN layer1
__device__ __half g_H1h[(size_t)RR*H1];    // post-BN+ReLU layer1 (fp16)
__device__ float  g_Y2 [(size_t)RR*H2];
__device__ float  g_bnsum[NRB*H1], g_bnsq[NRB*H1];
__device__ float  g_mean[H1], g_istd[H1];
__device__ float  g_regpart[18*16];
__device__ __half g_W1sh[(size_t)H1*SD];   // W1[:, 0:512]  fp16
__device__ __half g_W1vh[(size_t)H1*XV];   // W1[:, 512:1024] fp16
__device__ __half g_W2h[(size_t)H2*H1];
__device__ __half g_wihfh[G4*ED], g_wihrh[G4*ED];
__device__ __half g_stateh[(size_t)BB*SD];

// ---------------- cp.async helpers ----------------
__device__ __forceinline__ void cp16(void* sm, const void* g) {
    uint32_t a = (uint32_t)__cvta_generic_to_shared(sm);
    asm volatile("cp.async.ca.shared.global [%0], [%1], 16;\n" :: "r"(a), "l"(g));
}
__device__ __forceinline__ void cp_commit() { asm volatile("cp.async.commit_group;\n"); }
template<int N> __device__ __forceinline__ void cp_wait() {
    asm volatile("cp.async.wait_group %0;\n" :: "n"(N));
}

// ---------------- fp32 -> fp16 converts ----------------
__global__ void tohalf(const float* __restrict__ src, __half* __restrict__ dst, int n) {
    int i = blockIdx.x * blockDim.x + threadIdx.x;
    if (i < n) dst[i] = __float2half(src[i]);
}
// dst[r*cols + c] = src[r*src_ld + src_off + c]
__global__ void tohalf_strided(const float* __restrict__ src, __half* __restrict__ dst,
                               int rows, int src_ld, int src_off, int cols) {
    int i = blockIdx.x * blockDim.x + threadIdx.x;
    if (i >= rows * cols) return;
    const int r = i / cols, c = i - r * cols;
    dst[i] = __float2half(src[(size_t)r * src_ld + src_off + c]);
}

// ---------------- fp16 wmma GEMM, 3-stage cp.async ----------------
// C[M,N] = A[M,K] * B[N,K]^T (+ optional row-broadcast bias), fp32 accumulate.
// 256 threads (8 warps); CTA tile 128x128; warp tile 64x32; HLD_=40 (conflict-free).
// MODE 0: plain store. MODE 1: store + BN stats (re-read own tile).
// MODE 2: smem-staged epilogue: += rowbias[(brow+r)>>5], store, BN stats.
#define HBM_ 128
#define HBN_ 128
#define HBK_ 32
#define HLD_ 40
#define STG_ 3
#define HTILE (HBM_ * HLD_)
#define HG_SMEM (STG_ * 2 * HTILE * 2)   // 61440 bytes
#define EPLD 132                          // staging stride (floats)

template<int MODE>
__global__ __launch_bounds__(256, 2)
void hgemm_nt(const __half* __restrict__ A, int lda,
              const __half* __restrict__ B, int ldb,
              float* __restrict__ C, int N, int K,
              const float* __restrict__ rowbias) {
    extern __shared__ __align__(16) char dynsm[];
    __half* As = (__half*)dynsm;
    __half* Bs = As + STG_ * HTILE;

    const int tid   = threadIdx.x;
    const int brow  = blockIdx.y * HBM_;
    const int bcol  = blockIdx.x * HBN_;
    const int warpid = tid >> 5;
    const int wm = warpid & 1;   // 64-row slab
    const int wn = warpid >> 1;  // 32-col slab

    wmma::fragment<wmma::accumulator, 16, 16, 16, float> c[4][2];
    #pragma unroll
    for (int i = 0; i < 4; i++)
        #pragma unroll
        for (int j = 0; j < 2; j++) wmma::fill_fragment(c[i][j], 0.0f);

    const int lr = tid >> 2;          // 0..63
    const int lc = (tid & 3) * 8;     // halves

    auto issue = [&](int st, int k0) {
        #pragma unroll
        for (int s = 0; s < 2; s++) {
            const int r = lr + s * 64;
            cp16(&As[st * HTILE + r * HLD_ + lc], &A[(size_t)(brow + r) * lda + k0 + lc]);
            cp16(&Bs[st * HTILE + r * HLD_ + lc], &B[(size_t)(bcol + r) * ldb + k0 + lc]);
        }
        cp_commit();
    };

    const int nt = K / HBK_;
    issue(0, 0); issue(1, HBK_); issue(2, 2 * HBK_);

    for (int i = 0; i < nt; i++) {
        const int st = i % STG_;
        if (i <= nt - STG_)      cp_wait<STG_-1>();
        else if (i == nt - 2)    cp_wait<1>();
        else                     cp_wait<0>();
        __syncthreads();

        #pragma unroll
        for (int kk = 0; kk < HBK_; kk += 16) {
            wmma::fragment<wmma::matrix_a, 16, 16, 16, __half, wmma::row_major> af[4];
            wmma::fragment<wmma::matrix_b, 16, 16, 16, __half, wmma::col_major> bf[2];
            #pragma unroll
            for (int ii = 0; ii < 4; ii++)
                wmma::load_matrix_sync(af[ii], &As[st * HTILE + (wm * 64 + ii * 16) * HLD_ + kk], HLD_);
            #pragma unroll
            for (int j = 0; j < 2; j++)
                wmma::load_matrix_sync(bf[j], &Bs[st * HTILE + (wn * 32 + j * 16) * HLD_ + kk], HLD_);
            #pragma unroll
            for (int ii = 0; ii < 4; ii++)
                #pragma unroll
                for (int j = 0; j < 2; j++)
                    wmma::mma_sync(c[ii][j], af[ii], bf[j], c[ii][j]);
        }
        __syncthreads();
        if (i + STG_ < nt) issue(st, (i + STG_) * HBK_);
    }

    if (MODE == 2) {
        // smem-staged epilogue with row-broadcast bias + BN stats
        float* stage = (float*)dynsm;            // 64 x EPLD floats = 33.8KB
        const int col = tid & 127;
        const int rh  = tid >> 7;                // 0..1
        float s = 0.f, s2 = 0.f;
        #pragma unroll
        for (int half = 0; half < 2; half++) {
            if (wm == half) {
                #pragma unroll
                for (int i = 0; i < 4; i++)
                    #pragma unroll
                    for (int j = 0; j < 2; j++)
                        wmma::store_matrix_sync(&stage[(i * 16) * EPLD + wn * 32 + j * 16],
                                                c[i][j], EPLD, wmma::mem_row_major);
            }
            __syncthreads();
            #pragma unroll 4
            for (int rr = 0; rr < 32; rr++) {
                const int r = rh * 32 + rr;                 // 0..63 within half
                const int gr = brow + half * 64 + r;
                const float bias = rowbias[(size_t)(gr >> 5) * N + bcol + col];
                const float v = stage[r * EPLD + col] + bias;
                C[(size_t)gr * N + bcol + col] = v;
                s += v; s2 += v * v;
            }
            __syncthreads();
        }
        __shared__ float redS[256], redQ[256];
        redS[tid] = s; redQ[tid] = s2;
        __syncthreads();
        if (tid < 128) {
            g_bnsum[(size_t)blockIdx.y * N + bcol + tid] = redS[tid] + redS[tid + 128];
            g_bnsq [(size_t)blockIdx.y * N + bcol + tid] = redQ[tid] + redQ[tid + 128];
        }
        return;
    }

    #pragma unroll
    for (int i = 0; i < 4; i++)
        #pragma unroll
        for (int j = 0; j < 2; j++)
            wmma::store_matrix_sync(
                &C[(size_t)(brow + wm * 64 + i * 16) * N + bcol + wn * 32 + j * 16],
                c[i][j], N, wmma::mem_row_major);

    if (MODE == 1) {
        __syncthreads();
        __shared__ float redS[256], redQ[256];
        const int col = tid & 127;
        const int hh  = tid >> 7;
        const float* cp = C + (size_t)(brow + hh * 64) * N + bcol + col;
        float s = 0.f, s2 = 0.f;
        #pragma unroll 8
        for (int r = 0; r < 64; r++) {
            float v = cp[(size_t)r * N];
            s += v; s2 += v * v;
        }
        redS[tid] = s; redQ[tid] = s2;
        __syncthreads();
        if (tid < 128) {
            g_bnsum[(size_t)blockIdx.y * N + bcol + tid] = redS[tid] + redS[tid + 128];
            g_bnsq [(size_t)blockIdx.y * N + bcol + tid] = redQ[tid] + redQ[tid + 128];
        }
    }
}

// ---------------- persistent fused bidirectional LSTM ----------------
#define LROWS 32
#define LHLD  136
#define GLD   520
#define LSMEM_G     0
#define LSMEM_BIAS  (LSMEM_G + LROWS * GLD * 4)
#define LSMEM_WHH   (LSMEM_BIAS + G4 * 4)
#define LSMEM_H     (LSMEM_WHH + G4 * LHLD * 2)
#define LSMEM_TOTAL (LSMEM_H + LROWS * LHLD * 2)

__global__ __launch_bounds__(256, 1)
void lstm_fused(const float* __restrict__ whh_f, const float* __restrict__ whh_r,
                const float* __restrict__ bihf, const float* __restrict__ bhhf,
                const float* __restrict__ bihr, const float* __restrict__ bhhr) {
    extern __shared__ char smem[];
    float*  sG    = (float*)(smem + LSMEM_G);
    float*  sBias = (float*)(smem + LSMEM_BIAS);
    __half* sWhh  = (__half*)(smem + LSMEM_WHH);
    __half* sH    = (__half*)(smem + LSMEM_H);

    const int z  = blockIdx.y;
    const int b0 = blockIdx.x * LROWS;
    const int tid = threadIdx.x;
    const int warpid = tid >> 5;

    const float* Whh = z ? whh_r : whh_f;
    const float* XP  = z ? g_XPr : g_XPf;
    const float* bih = z ? bihr : bihf;
    const float* bhh = z ? bhhr : bhhf;
    const int colbase = z ? 128 : 0;   // Of at 0:128, Or at 128:256 of Xv

    for (int i = tid; i < G4 * HH; i += 256) {
        const int n = i >> 7, k = i & 127;
        sWhh[n * LHLD + k] = __float2half(Whh[i]);
    }
    for (int i = tid; i < G4; i += 256) sBias[i] = bih[i] + bhh[i];
    for (int i = tid; i < LROWS * LHLD; i += 256) sH[i] = __float2half(0.f);

    float creg[16];
    #pragma unroll
    for (int e = 0; e < 16; e++) creg[e] = 0.f;
    __syncthreads();

    for (int t = 0; t < KK; t++) {
        const int k = z ? (KK - 1 - t) : t;
        {
            wmma::fragment<wmma::accumulator, 16, 16, 16, float> acc[2][4];
            #pragma unroll
            for (int i = 0; i < 2; i++)
                #pragma unroll
                for (int j = 0; j < 4; j++) wmma::fill_fragment(acc[i][j], 0.0f);

            #pragma unroll
            for (int kk = 0; kk < HH; kk += 16) {
                wmma::fragment<wmma::matrix_a, 16, 16, 16, __half, wmma::row_major> a0, a1;
                wmma::load_matrix_sync(a0, &sH[0 * LHLD + kk], LHLD);
                wmma::load_matrix_sync(a1, &sH[16 * LHLD + kk], LHLD);
                #pragma unroll
                for (int j = 0; j < 4; j++) {
                    wmma::fragment<wmma::matrix_b, 16, 16, 16, __half, wmma::col_major> bfr;
                    wmma::load_matrix_sync(bfr, &sWhh[(warpid * 64 + j * 16) * LHLD + kk], LHLD);
                    wmma::mma_sync(acc[0][j], a0, bfr, acc[0][j]);
                    wmma::mma_sync(acc[1][j], a1, bfr, acc[1][j]);
                }
            }
            #pragma unroll
            for (int i = 0; i < 2; i++)
                #pragma unroll
                for (int j = 0; j < 4; j++)
                    wmma::store_matrix_sync(&sG[(i * 16) * GLD + warpid * 64 + j * 16],
                                            acc[i][j], GLD, wmma::mem_row_major);
        }
        __syncthreads();

        #pragma unroll
        for (int e = 0; e < 16; e++) {
            const int idx = tid + 256 * e;
            const int row = idx >> 7;
            const int j   = idx & 127;
            const size_t r = (size_t)(b0 + row) * KK + k;
            const float* xp = XP + r * G4;
            const float* gr = sG + row * GLD;

            const float zi = xp[j]       + gr[j]       + sBias[j];
            const float zf = xp[128 + j] + gr[128 + j] + sBias[128 + j];
            const float zg = xp[256 + j] + gr[256 + j] + sBias[256 + j];
            const float zo = xp[384 + j] + gr[384 + j] + sBias[384 + j];

            const float si = 1.f / (1.f + expf(-zi));
            const float sf = 1.f / (1.f + expf(-zf));
            const float so = 1.f / (1.f + expf(-zo));

            const float cn = sf * creg[e] + si * tanhf(zg);
            const float hn = so * tanhf(cn);
            creg[e] = cn;

            sH[row * LHLD + j] = __float2half(hn);
            g_Xv[r * XV + colbase + j] = __float2half(hn);
        }
        __syncthreads();
    }
}

// ---------------- fill V into Xv (cols 256:384) ----------------
__global__ void fill_V(const float* __restrict__ action) {
    const int i = blockIdx.x * blockDim.x + threadIdx.x;   // over RR*128
    if (i >= RR * ED) return;
    const int r = i >> 7, d = i & 127;
    g_Xv[(size_t)r * XV + 256 + d] = __float2half(action[i]);
}

// ---------------- self-attention, register-blocked ----------------
#define VLD 133
__global__ __launch_bounds__(128)
void attn_kernel(const float* __restrict__ V) {
    const int b = blockIdx.x;
    __shared__ float sV[32 * VLD];
    __shared__ float sS[32 * 33];
    const int tid = threadIdx.x;  // 128
    const float* Vb = V + (size_t)b * KK * ED;

    for (int i = tid; i < KK * ED; i += 128)
        sV[(i >> 7) * VLD + (i & 127)] = Vb[i];
    __syncthreads();

    {
        const int rp = tid >> 3;
        const int cq = tid & 7;
        float acc[2][4];
        #pragma unroll
        for (int i = 0; i < 2; i++)
            #pragma unroll
            for (int j = 0; j < 4; j++) acc[i][j] = 0.f;

        #pragma unroll 4
        for (int d = 0; d < ED; d++) {
            const float a0 = sV[(2 * rp)     * VLD + d];
            const float a1 = sV[(2 * rp + 1) * VLD + d];
            #pragma unroll
            for (int j = 0; j < 4; j++) {
                const float bv = sV[(4 * cq + j) * VLD + d];
                acc[0][j] += a0 * bv;
                acc[1][j] += a1 * bv;
            }
        }
        #pragma unroll
        for (int i = 0; i < 2; i++)
            #pragma unroll
            for (int j = 0; j < 4; j++)
                sS[(2 * rp + i) * 33 + 4 * cq + j] = acc[i][j];
    }
    __syncthreads();

    if (tid < KK) {
        float mx = -1e30f;
        for (int c = 0; c < KK; c++) mx = fmaxf(mx, sS[tid * 33 + c]);
        float sum = 0.f;
        for (int c = 0; c < KK; c++) { float e = expf(sS[tid * 33 + c] - mx); sS[tid * 33 + c] = e; sum += e; }
        float inv = 1.f / sum;
        for (int c = 0; c < KK; c++) sS[tid * 33 + c] *= inv;
    }
    __syncthreads();

    {
        float a[32];
        #pragma unroll
        for (int k = 0; k < 32; k++) a[k] = 0.f;
        #pragma unroll 4
        for (int l = 0; l < 32; l++) {
            const float vl = sV[l * VLD + tid];
            #pragma unroll
            for (int k = 0; k < 32; k++) a[k] += sS[k * 33 + l] * vl;
        }
        #pragma unroll
        for (int k = 0; k < 32; k++) {
            const size_t r = (size_t)b * KK + k;
            g_Xv[r * XV + 384 + tid] = __float2half(a[k]);
        }
    }
}

// ---------------- BN finalize over 1024 row-block partials ----------------
__global__ void bn_finalize(int cols) {
    const int c = blockIdx.x * 128 + threadIdx.x;
    float s = 0.f, s2 = 0.f;
    for (int rb = 0; rb < NRB; rb++) {
        s  += g_bnsum[(size_t)rb * cols + c];
        s2 += g_bnsq [(size_t)rb * cols + c];
    }
    const float mu  = s  / (float)RR;
    const float var = s2 / (float)RR - mu * mu;
    g_mean[c] = mu;
    g_istd[c] = rsqrtf(var + 1e-5f);
}

// ---------------- layer-1 BN+ReLU -> fp16 ----------------
__global__ void bn_apply_relu_h(const float* __restrict__ Y, __half* __restrict__ out,
                                const float* __restrict__ gamma,
                                const float* __restrict__ beta, int cols) {
    const size_t total = (size_t)RR * cols;
    const int mask = cols - 1;
    size_t i = (size_t)blockIdx.x * blockDim.x + threadIdx.x;
    const size_t stride = (size_t)gridDim.x * blockDim.x;
    for (; i < total; i += stride) {
        const int c = (int)(i & mask);
        float v = (Y[i] - g_mean[c]) * g_istd[c] * gamma[c] + beta[c];
        out[i] = __float2half(v > 0.f ? v : 0.f);
    }
}

// ---------------- final layer with fused layer-2 BN+ReLU ----------------
__global__ __launch_bounds__(256)
void final_q(const float* __restrict__ W3, const float* __restrict__ b3,
             const float* __restrict__ g2, const float* __restrict__ be2,
             float* __restrict__ out) {
    __shared__ float sw[H2], smu[H2], sis[H2], sg[H2], sb[H2];
    const int tid = threadIdx.x;
    for (int i = tid; i < H2; i += 256) {
        sw[i] = W3[i]; smu[i] = g_mean[i]; sis[i] = g_istd[i];
        sg[i] = g2[i]; sb[i] = be2[i];
    }
    __syncthreads();

    const int warp = tid >> 5, lane = tid & 31;
    const size_t row = (size_t)blockIdx.x * 8 + warp;
    const float* y = g_Y2 + row * H2;
    float s = 0.f;
    #pragma unroll
    for (int i = 0; i < H2 / 32; i++) {
        const int c = i * 32 + lane;
        float v = (y[c] - smu[c]) * sis[c] * sg[c] + sb[c];
        v = fmaxf(v, 0.f);
        s += v * sw[c];
    }
    #pragma unroll
    for (int o = 16; o; o >>= 1) s += __shfl_xor_sync(0xffffffffu, s, o);
    if (lane == 0) out[row] = s + b3[0];
}

// ---------------- regularizer ----------------
struct RegArgs { const float* p[18]; int n[18]; };

__global__ void reg_partial(RegArgs ra) {
    const int pi = blockIdx.x;
    const int ch = blockIdx.y;
    __shared__ float red[256];
    const float* p = ra.p[pi];
    const int n = ra.n[pi];
    const int per = (n + 15) / 16;
    const int lo = ch * per;
    const int hi = min(n, lo + per);
    float s = 0.f;
    for (int i = lo + threadIdx.x; i < hi; i += 256) { float v = p[i]; s += v * v; }
    red[threadIdx.x] = s;
    __syncthreads();
    for (int o = 128; o; o >>= 1) {
        if (threadIdx.x < o) red[threadIdx.x] += red[threadIdx.x + o];
        __syncthreads();
    }
    if (threadIdx.x == 0) g_regpart[pi * 16 + ch] = red[0] / (float)n;
}

__global__ void reg_final(float* out, int out_size) {
    if (threadIdx.x == 0 && blockIdx.x == 0) {
        float s = 0.f;
        for (int i = 0; i < 18 * 16; i++) s += g_regpart[i];
        if (out_size > RR) out[RR] = s;
    }
}

// ---------------- launch ----------------
extern "C" void kernel_launch(void* const* d_in, const int* in_sizes, int n_in,
                              void* d_out, int out_size) {
    const float* state  = (const float*)d_in[0];
    const float* action = (const float*)d_in[1];
    const float* w_ih_f = (const float*)d_in[2];
    const float* w_hh_f = (const float*)d_in[3];
    const float* b_ih_f = (const float*)d_in[4];
    const float* b_hh_f = (const float*)d_in[5];
    const float* w_ih_r = (const float*)d_in[6];
    const float* w_hh_r = (const float*)d_in[7];
    const float* b_ih_r = (const float*)d_in[8];
    const float* b_hh_r = (const float*)d_in[9];
    const float* W1 = (const float*)d_in[10];
    const float* g1 = (const float*)d_in[12];
    const float* be1 = (const float*)d_in[13];
    const float* W2 = (const float*)d_in[14];
    const float* g2 = (const float*)d_in[16];
    const float* be2 = (const float*)d_in[17];
    const float* W3 = (const float*)d_in[18];
    const float* b3 = (const float*)d_in[19];
    float* out = (float*)d_out;

    float *pXPf, *pXPr, *pY1s, *pY1, *pY2;
    __half *pXv, *pH1h, *pW1sh, *pW1vh, *pW2h, *pwfh, *pwrh, *pSh;
    cudaGetSymbolAddress((void**)&pXPf, g_XPf);
    cudaGetSymbolAddress((void**)&pXPr, g_XPr);
    cudaGetSymbolAddress((void**)&pXv,  g_Xv);
    cudaGetSymbolAddress((void**)&pY1s, g_Y1s);
    cudaGetSymbolAddress((void**)&pY1,  g_Y1);
    cudaGetSymbolAddress((void**)&pH1h, g_H1h);
    cudaGetSymbolAddress((void**)&pY2,  g_Y2);
    cudaGetSymbolAddress((void**)&pW1sh, g_W1sh);
    cudaGetSymbolAddress((void**)&pW1vh, g_W1vh);
    cudaGetSymbolAddress((void**)&pW2h, g_W2h);
    cudaGetSymbolAddress((void**)&pwfh, g_wihfh);
    cudaGetSymbolAddress((void**)&pwrh, g_wihrh);
    cudaGetSymbolAddress((void**)&pSh,  g_stateh);

    cudaFuncSetAttribute(lstm_fused, cudaFuncAttributeMaxDynamicSharedMemorySize, LSMEM_TOTAL);
    cudaFuncSetAttribute(hgemm_nt<0>, cudaFuncAttributeMaxDynamicSharedMemorySize, HG_SMEM);
    cudaFuncSetAttribute(hgemm_nt<1>, cudaFuncAttributeMaxDynamicSharedMemorySize, HG_SMEM);
    cudaFuncSetAttribute(hgemm_nt<2>, cudaFuncAttributeMaxDynamicSharedMemorySize, HG_SMEM);

    // 0. weight/state conversions (tiny)
    tohalf_strided<<<(H1*SD + 255)/256, 256>>>(W1, pW1sh, H1, MLPIN, 0,  SD);
    tohalf_strided<<<(H1*XV + 255)/256, 256>>>(W1, pW1vh, H1, MLPIN, SD, XV);
    tohalf<<<(H2*H1 + 255)/256, 256>>>(W2, pW2h, H2*H1);
    tohalf<<<(G4*ED + 255)/256, 256>>>(w_ih_f, pwfh, G4*ED);
    tohalf<<<(G4*ED + 255)/256, 256>>>(w_ih_r, pwrh, G4*ED);
    tohalf<<<(BB*SD + 255)/256, 256>>>(state, pSh, BB*SD);

    // 1. V into Xv
    fill_V<<<(RR*ED + 255)/256, 256>>>(action);

    // 2. attention -> Xv[:,384:512]
    attn_kernel<<<BB, 128>>>(action);

    // 3. x_proj both directions (A = V columns of Xv)
    hgemm_nt<0><<<dim3(G4/HBN_, RR/HBM_), 256, HG_SMEM>>>(pXv + 256, XV, pwfh, ED, pXPf, G4, ED, nullptr);
    hgemm_nt<0><<<dim3(G4/HBN_, RR/HBM_), 256, HG_SMEM>>>(pXv + 256, XV, pwrh, ED, pXPr, G4, ED, nullptr);

    // 3b. Y1s = state @ W1s^T   [4096 x 1024], exact S-factorization of MLP1
    hgemm_nt<0><<<dim3(H1/HBN_, BB/HBM_), 256, HG_SMEM>>>(pSh, SD, pW1sh, SD, pY1s, H1, SD, nullptr);

    // 4. fused persistent LSTM (both directions)
    lstm_fused<<<dim3(BB/LROWS, 2), 256, LSMEM_TOTAL>>>(w_hh_f, w_hh_r,
                                                        b_ih_f, b_hh_f, b_ih_r, b_hh_r);

    // 5. MLP layer 1: Y1 = Xv @ W1v^T + broadcast(Y1s), fused BN stats
    hgemm_nt<2><<<dim3(H1/HBN_, RR/HBM_), 256, HG_SMEM>>>(pXv, XV, pW1vh, XV, pY1, H1, XV, pY1s);
    bn_finalize<<<H1/128, 128>>>(H1);
    bn_apply_relu_h<<<2048, 256>>>(pY1, pH1h, g1, be1, H1);

    // 6. MLP layer 2 + fused BN stats
    hgemm_nt<1><<<dim3(H2/HBN_, RR/HBM_), 256, HG_SMEM>>>(pH1h, H1, pW2h, H1, pY2, H2, H1, nullptr);
    bn_finalize<<<H2/128, 128>>>(H2);

    // 7. final layer with fused layer-2 BN+ReLU
    final_q<<<RR/8, 256>>>(W3, b3, g2, be2, out);

    // 8. regularizer
    {
        RegArgs ra;
        for (int i = 0; i < 18; i++) {
            ra.p[i] = (const float*)d_in[2 + i];
            ra.n[i] = in_sizes[2 + i];
        }
        reg_partial<<<dim3(18, 16), 256>>>(ra);
        reg_final<<<1, 32>>>(out, out_size);
    }
}

// round 17
// speedup vs baseline: 1.4477x; 1.0219x over previous
#include <cuda_runtime.h>
#include <cuda_fp16.h>
#include <mma.h>
#include <math.h>
#include <stdint.h>

using namespace nvcuda;

// ---------------- problem constants ----------------
#define BB 4096
#define KK 32
#define SD 512          // STATE_DIM
#define ED 128          // ENC_DIM
#define HH 128          // H
#define G4 512          // 4*H
#define RR (BB*KK)      // 131072 rows
#define MLPIN 1024
#define XV 512          // reduced MLP input cols (Of|Or|V|A)
#define H1 1024
#define H2 512
#define NRB (RR/128)    // 1024 GEMM row-blocks

// ---------------- device scratch (all intermediates fp16) ----------------
__device__ __half g_XPf[(size_t)RR*G4];    // x_proj forward
__device__ __half g_XPr[(size_t)RR*G4];    // x_proj reverse
__device__ __half g_Xv [(size_t)RR*XV];    // MLP input (Of|Or|V|A)
__device__ __half g_Y1s[(size_t)BB*H1];    // state @ W1s^T
__device__ __half g_Y1 [(size_t)RR*H1];    // pre-BN layer1
__device__ __half g_H1h[(size_t)RR*H1];    // post-BN+ReLU layer1
__device__ __half g_Y2 [(size_t)RR*H2];
__device__ float  g_bnsum[NRB*H1], g_bnsq[NRB*H1];
__device__ float  g_mean[H1], g_istd[H1];
__device__ float  g_regpart[18*16];
__device__ __half g_W1sh[(size_t)H1*SD];
__device__ __half g_W1vh[(size_t)H1*XV];
__device__ __half g_W2h[(size_t)H2*H1];
__device__ __half g_wihfh[G4*ED], g_wihrh[G4*ED];
__device__ __half g_stateh[(size_t)BB*SD];

// ---------------- cp.async helpers ----------------
__device__ __forceinline__ void cp16(void* sm, const void* g) {
    uint32_t a = (uint32_t)__cvta_generic_to_shared(sm);
    asm volatile("cp.async.ca.shared.global [%0], [%1], 16;\n" :: "r"(a), "l"(g));
}
__device__ __forceinline__ void cp_commit() { asm volatile("cp.async.commit_group;\n"); }
template<int N> __device__ __forceinline__ void cp_wait() {
    asm volatile("cp.async.wait_group %0;\n" :: "n"(N));
}

// ---------------- fp32 -> fp16 converts ----------------
__global__ void tohalf(const float* __restrict__ src, __half* __restrict__ dst, int n) {
    int i = blockIdx.x * blockDim.x + threadIdx.x;
    if (i < n) dst[i] = __float2half(src[i]);
}
__global__ void tohalf_strided(const float* __restrict__ src, __half* __restrict__ dst,
                               int rows, int src_ld, int src_off, int cols) {
    int i = blockIdx.x * blockDim.x + threadIdx.x;
    if (i >= rows * cols) return;
    const int r = i / cols, c = i - r * cols;
    dst[i] = __float2half(src[(size_t)r * src_ld + src_off + c]);
}

// ---------------- fp16 wmma GEMM, 3-stage cp.async, staged fp16 epilogue ----
// C(fp16)[M,N] = A[M,K] * B[N,K]^T (+ optional fp16 row-broadcast bias).
// 256 threads (8 warps); CTA tile 128x128; warp tile 64x32; HLD_=40 (conflict-free).
// MODE 0: plain fp16 store. MODE 1: fp16 store + BN stats from staged tile.
// MODE 2: += rowbias[(gr)>>5] then fp16 store + BN stats.
#define HBM_ 128
#define HBN_ 128
#define HBK_ 32
#define HLD_ 40
#define STG_ 3
#define HTILE (HBM_ * HLD_)
#define HG_SMEM (STG_ * 2 * HTILE * 2)   // 61440 bytes
#define EPLD 132                          // staging stride (floats)

template<int MODE>
__global__ __launch_bounds__(256, 2)
void hgemm_nt(const __half* __restrict__ A, int lda,
              const __half* __restrict__ B, int ldb,
              __half* __restrict__ C, int N, int K,
              const __half* __restrict__ rowbias) {
    extern __shared__ __align__(16) char dynsm[];
    __half* As = (__half*)dynsm;
    __half* Bs = As + STG_ * HTILE;

    const int tid   = threadIdx.x;
    const int brow  = blockIdx.y * HBM_;
    const int bcol  = blockIdx.x * HBN_;
    const int warpid = tid >> 5;
    const int wm = warpid & 1;   // 64-row slab
    const int wn = warpid >> 1;  // 32-col slab

    wmma::fragment<wmma::accumulator, 16, 16, 16, float> c[4][2];
    #pragma unroll
    for (int i = 0; i < 4; i++)
        #pragma unroll
        for (int j = 0; j < 2; j++) wmma::fill_fragment(c[i][j], 0.0f);

    const int lr = tid >> 2;          // 0..63
    const int lc = (tid & 3) * 8;     // halves

    auto issue = [&](int st, int k0) {
        #pragma unroll
        for (int s = 0; s < 2; s++) {
            const int r = lr + s * 64;
            cp16(&As[st * HTILE + r * HLD_ + lc], &A[(size_t)(brow + r) * lda + k0 + lc]);
            cp16(&Bs[st * HTILE + r * HLD_ + lc], &B[(size_t)(bcol + r) * ldb + k0 + lc]);
        }
        cp_commit();
    };

    const int nt = K / HBK_;
    issue(0, 0); issue(1, HBK_); issue(2, 2 * HBK_);

    for (int i = 0; i < nt; i++) {
        const int st = i % STG_;
        if (i <= nt - STG_)      cp_wait<STG_-1>();
        else if (i == nt - 2)    cp_wait<1>();
        else                     cp_wait<0>();
        __syncthreads();

        #pragma unroll
        for (int kk = 0; kk < HBK_; kk += 16) {
            wmma::fragment<wmma::matrix_a, 16, 16, 16, __half, wmma::row_major> af[4];
            wmma::fragment<wmma::matrix_b, 16, 16, 16, __half, wmma::col_major> bf[2];
            #pragma unroll
            for (int ii = 0; ii < 4; ii++)
                wmma::load_matrix_sync(af[ii], &As[st * HTILE + (wm * 64 + ii * 16) * HLD_ + kk], HLD_);
            #pragma unroll
            for (int j = 0; j < 2; j++)
                wmma::load_matrix_sync(bf[j], &Bs[st * HTILE + (wn * 32 + j * 16) * HLD_ + kk], HLD_);
            #pragma unroll
            for (int ii = 0; ii < 4; ii++)
                #pragma unroll
                for (int j = 0; j < 2; j++)
                    wmma::mma_sync(c[ii][j], af[ii], bf[j], c[ii][j]);
        }
        __syncthreads();
        if (i + STG_ < nt) issue(st, (i + STG_) * HBK_);
    }

    // staged epilogue: fragments -> smem -> (bias) -> fp16 store (+ stats)
    float* stage = (float*)dynsm;            // 64 x EPLD floats
    const int col = tid & 127;
    const int rh  = tid >> 7;                // 0..1
    float s = 0.f, s2 = 0.f;
    #pragma unroll
    for (int half = 0; half < 2; half++) {
        if (wm == half) {
            #pragma unroll
            for (int i = 0; i < 4; i++)
                #pragma unroll
                for (int j = 0; j < 2; j++)
                    wmma::store_matrix_sync(&stage[(i * 16) * EPLD + wn * 32 + j * 16],
                                            c[i][j], EPLD, wmma::mem_row_major);
        }
        __syncthreads();
        #pragma unroll 4
        for (int rr = 0; rr < 32; rr++) {
            const int r = rh * 32 + rr;
            const int gr = brow + half * 64 + r;
            float v = stage[r * EPLD + col];
            if (MODE == 2)
                v += __half2float(rowbias[(size_t)(gr >> 5) * N + bcol + col]);
            if (MODE >= 1) { s += v; s2 += v * v; }
            C[(size_t)gr * N + bcol + col] = __float2half(v);
        }
        __syncthreads();
    }

    if (MODE >= 1) {
        __shared__ float redS[256], redQ[256];
        redS[tid] = s; redQ[tid] = s2;
        __syncthreads();
        if (tid < 128) {
            g_bnsum[(size_t)blockIdx.y * N + bcol + tid] = redS[tid] + redS[tid + 128];
            g_bnsq [(size_t)blockIdx.y * N + bcol + tid] = redQ[tid] + redQ[tid + 128];
        }
    }
}

// ---------------- persistent fused bidirectional LSTM ----------------
#define LROWS 32
#define LHLD  136
#define GLD   520
#define LSMEM_G     0
#define LSMEM_BIAS  (LSMEM_G + LROWS * GLD * 4)
#define LSMEM_WHH   (LSMEM_BIAS + G4 * 4)
#define LSMEM_H     (LSMEM_WHH + G4 * LHLD * 2)
#define LSMEM_TOTAL (LSMEM_H + LROWS * LHLD * 2)

__global__ __launch_bounds__(256, 1)
void lstm_fused(const float* __restrict__ whh_f, const float* __restrict__ whh_r,
                const float* __restrict__ bihf, const float* __restrict__ bhhf,
                const float* __restrict__ bihr, const float* __restrict__ bhhr) {
    extern __shared__ char smem[];
    float*  sG    = (float*)(smem + LSMEM_G);
    float*  sBias = (float*)(smem + LSMEM_BIAS);
    __half* sWhh  = (__half*)(smem + LSMEM_WHH);
    __half* sH    = (__half*)(smem + LSMEM_H);

    const int z  = blockIdx.y;
    const int b0 = blockIdx.x * LROWS;
    const int tid = threadIdx.x;
    const int warpid = tid >> 5;

    const float* Whh = z ? whh_r : whh_f;
    const __half* XP = z ? g_XPr : g_XPf;
    const float* bih = z ? bihr : bihf;
    const float* bhh = z ? bhhr : bhhf;
    const int colbase = z ? 128 : 0;   // Of at 0:128, Or at 128:256 of Xv

    for (int i = tid; i < G4 * HH; i += 256) {
        const int n = i >> 7, k = i & 127;
        sWhh[n * LHLD + k] = __float2half(Whh[i]);
    }
    for (int i = tid; i < G4; i += 256) sBias[i] = bih[i] + bhh[i];
    for (int i = tid; i < LROWS * LHLD; i += 256) sH[i] = __float2half(0.f);

    float creg[16];
    #pragma unroll
    for (int e = 0; e < 16; e++) creg[e] = 0.f;
    __syncthreads();

    for (int t = 0; t < KK; t++) {
        const int k = z ? (KK - 1 - t) : t;
        {
            wmma::fragment<wmma::accumulator, 16, 16, 16, float> acc[2][4];
            #pragma unroll
            for (int i = 0; i < 2; i++)
                #pragma unroll
                for (int j = 0; j < 4; j++) wmma::fill_fragment(acc[i][j], 0.0f);

            #pragma unroll
            for (int kk = 0; kk < HH; kk += 16) {
                wmma::fragment<wmma::matrix_a, 16, 16, 16, __half, wmma::row_major> a0, a1;
                wmma::load_matrix_sync(a0, &sH[0 * LHLD + kk], LHLD);
                wmma::load_matrix_sync(a1, &sH[16 * LHLD + kk], LHLD);
                #pragma unroll
                for (int j = 0; j < 4; j++) {
                    wmma::fragment<wmma::matrix_b, 16, 16, 16, __half, wmma::col_major> bfr;
                    wmma::load_matrix_sync(bfr, &sWhh[(warpid * 64 + j * 16) * LHLD + kk], LHLD);
                    wmma::mma_sync(acc[0][j], a0, bfr, acc[0][j]);
                    wmma::mma_sync(acc[1][j], a1, bfr, acc[1][j]);
                }
            }
            #pragma unroll
            for (int i = 0; i < 2; i++)
                #pragma unroll
                for (int j = 0; j < 4; j++)
                    wmma::store_matrix_sync(&sG[(i * 16) * GLD + warpid * 64 + j * 16],
                                            acc[i][j], GLD, wmma::mem_row_major);
        }
        __syncthreads();

        #pragma unroll
        for (int e = 0; e < 16; e++) {
            const int idx = tid + 256 * e;
            const int row = idx >> 7;
            const int j   = idx & 127;
            const size_t r = (size_t)(b0 + row) * KK + k;
            const __half* xp = XP + r * G4;
            const float* gr = sG + row * GLD;

            const float zi = __half2float(xp[j])       + gr[j]       + sBias[j];
            const float zf = __half2float(xp[128 + j]) + gr[128 + j] + sBias[128 + j];
            const float zg = __half2float(xp[256 + j]) + gr[256 + j] + sBias[256 + j];
            const float zo = __half2float(xp[384 + j]) + gr[384 + j] + sBias[384 + j];

            const float si = 1.f / (1.f + expf(-zi));
            const float sf = 1.f / (1.f + expf(-zf));
            const float so = 1.f / (1.f + expf(-zo));

            const float cn = sf * creg[e] + si * tanhf(zg);
            const float hn = so * tanhf(cn);
            creg[e] = cn;

            sH[row * LHLD + j] = __float2half(hn);
            g_Xv[r * XV + colbase + j] = __float2half(hn);
        }
        __syncthreads();
    }
}

// ---------------- fill V into Xv (cols 256:384) ----------------
__global__ void fill_V(const float* __restrict__ action) {
    const int i = blockIdx.x * blockDim.x + threadIdx.x;
    if (i >= RR * ED) return;
    const int r = i >> 7, d = i & 127;
    g_Xv[(size_t)r * XV + 256 + d] = __float2half(action[i]);
}

// ---------------- self-attention, register-blocked ----------------
#define VLD 133
__global__ __launch_bounds__(128)
void attn_kernel(const float* __restrict__ V) {
    const int b = blockIdx.x;
    __shared__ float sV[32 * VLD];
    __shared__ float sS[32 * 33];
    const int tid = threadIdx.x;  // 128
    const float* Vb = V + (size_t)b * KK * ED;

    for (int i = tid; i < KK * ED; i += 128)
        sV[(i >> 7) * VLD + (i & 127)] = Vb[i];
    __syncthreads();

    {
        const int rp = tid >> 3;
        const int cq = tid & 7;
        float acc[2][4];
        #pragma unroll
        for (int i = 0; i < 2; i++)
            #pragma unroll
            for (int j = 0; j < 4; j++) acc[i][j] = 0.f;

        #pragma unroll 4
        for (int d = 0; d < ED; d++) {
            const float a0 = sV[(2 * rp)     * VLD + d];
            const float a1 = sV[(2 * rp + 1) * VLD + d];
            #pragma unroll
            for (int j = 0; j < 4; j++) {
                const float bv = sV[(4 * cq + j) * VLD + d];
                acc[0][j] += a0 * bv;
                acc[1][j] += a1 * bv;
            }
        }
        #pragma unroll
        for (int i = 0; i < 2; i++)
            #pragma unroll
            for (int j = 0; j < 4; j++)
                sS[(2 * rp + i) * 33 + 4 * cq + j] = acc[i][j];
    }
    __syncthreads();

    if (tid < KK) {
        float mx = -1e30f;
        for (int c = 0; c < KK; c++) mx = fmaxf(mx, sS[tid * 33 + c]);
        float sum = 0.f;
        for (int c = 0; c < KK; c++) { float e = expf(sS[tid * 33 + c] - mx); sS[tid * 33 + c] = e; sum += e; }
        float inv = 1.f / sum;
        for (int c = 0; c < KK; c++) sS[tid * 33 + c] *= inv;
    }
    __syncthreads();

    {
        float a[32];
        #pragma unroll
        for (int k = 0; k < 32; k++) a[k] = 0.f;
        #pragma unroll 4
        for (int l = 0; l < 32; l++) {
            const float vl = sV[l * VLD + tid];
            #pragma unroll
            for (int k = 0; k < 32; k++) a[k] += sS[k * 33 + l] * vl;
        }
        #pragma unroll
        for (int k = 0; k < 32; k++) {
            const size_t r = (size_t)b * KK + k;
            g_Xv[r * XV + 384 + tid] = __float2half(a[k]);
        }
    }
}

// ---------------- BN finalize over 1024 row-block partials ----------------
__global__ void bn_finalize(int cols) {
    const int c = blockIdx.x * 128 + threadIdx.x;
    float s = 0.f, s2 = 0.f;
    for (int rb = 0; rb < NRB; rb++) {
        s  += g_bnsum[(size_t)rb * cols + c];
        s2 += g_bnsq [(size_t)rb * cols + c];
    }
    const float mu  = s  / (float)RR;
    const float var = s2 / (float)RR - mu * mu;
    g_mean[c] = mu;
    g_istd[c] = rsqrtf(var + 1e-5f);
}

// ---------------- layer-1 BN+ReLU (fp16 in/out) ----------------
__global__ void bn_apply_relu_h(const __half* __restrict__ Y, __half* __restrict__ out,
                                const float* __restrict__ gamma,
                                const float* __restrict__ beta, int cols) {
    const size_t total = (size_t)RR * cols;
    const int mask = cols - 1;
    size_t i = (size_t)blockIdx.x * blockDim.x + threadIdx.x;
    const size_t stride = (size_t)gridDim.x * blockDim.x;
    for (; i < total; i += stride) {
        const int c = (int)(i & mask);
        float v = (__half2float(Y[i]) - g_mean[c]) * g_istd[c] * gamma[c] + beta[c];
        out[i] = __float2half(v > 0.f ? v : 0.f);
    }
}

// ---------------- final layer with fused layer-2 BN+ReLU (fp16 Y2) ----------
__global__ __launch_bounds__(256)
void final_q(const float* __restrict__ W3, const float* __restrict__ b3,
             const float* __restrict__ g2, const float* __restrict__ be2,
             float* __restrict__ out) {
    __shared__ float sw[H2], smu[H2], sis[H2], sg[H2], sb[H2];
    const int tid = threadIdx.x;
    for (int i = tid; i < H2; i += 256) {
        sw[i] = W3[i]; smu[i] = g_mean[i]; sis[i] = g_istd[i];
        sg[i] = g2[i]; sb[i] = be2[i];
    }
    __syncthreads();

    const int warp = tid >> 5, lane = tid & 31;
    const size_t row = (size_t)blockIdx.x * 8 + warp;
    const __half* y = g_Y2 + row * H2;
    float s = 0.f;
    #pragma unroll
    for (int i = 0; i < H2 / 32; i++) {
        const int c = i * 32 + lane;
        float v = (__half2float(y[c]) - smu[c]) * sis[c] * sg[c] + sb[c];
        v = fmaxf(v, 0.f);
        s += v * sw[c];
    }
    #pragma unroll
    for (int o = 16; o; o >>= 1) s += __shfl_xor_sync(0xffffffffu, s, o);
    if (lane == 0) out[row] = s + b3[0];
}

// ---------------- regularizer ----------------
struct RegArgs { const float* p[18]; int n[18]; };

__global__ void reg_partial(RegArgs ra) {
    const int pi = blockIdx.x;
    const int ch = blockIdx.y;
    __shared__ float red[256];
    const float* p = ra.p[pi];
    const int n = ra.n[pi];
    const int per = (n + 15) / 16;
    const int lo = ch * per;
    const int hi = min(n, lo + per);
    float s = 0.f;
    for (int i = lo + threadIdx.x; i < hi; i += 256) { float v = p[i]; s += v * v; }
    red[threadIdx.x] = s;
    __syncthreads();
    for (int o = 128; o; o >>= 1) {
        if (threadIdx.x < o) red[threadIdx.x] += red[threadIdx.x + o];
        __syncthreads();
    }
    if (threadIdx.x == 0) g_regpart[pi * 16 + ch] = red[0] / (float)n;
}

__global__ void reg_final(float* out, int out_size) {
    if (threadIdx.x == 0 && blockIdx.x == 0) {
        float s = 0.f;
        for (int i = 0; i < 18 * 16; i++) s += g_regpart[i];
        if (out_size > RR) out[RR] = s;
    }
}

// ---------------- launch ----------------
extern "C" void kernel_launch(void* const* d_in, const int* in_sizes, int n_in,
                              void* d_out, int out_size) {
    const float* state  = (const float*)d_in[0];
    const float* action = (const float*)d_in[1];
    const float* w_ih_f = (const float*)d_in[2];
    const float* w_hh_f = (const float*)d_in[3];
    const float* b_ih_f = (const float*)d_in[4];
    const float* b_hh_f = (const float*)d_in[5];
    const float* w_ih_r = (const float*)d_in[6];
    const float* w_hh_r = (const float*)d_in[7];
    const float* b_ih_r = (const float*)d_in[8];
    const float* b_hh_r = (const float*)d_in[9];
    const float* W1 = (const float*)d_in[10];
    const float* g1 = (const float*)d_in[12];
    const float* be1 = (const float*)d_in[13];
    const float* W2 = (const float*)d_in[14];
    const float* g2 = (const float*)d_in[16];
    const float* be2 = (const float*)d_in[17];
    const float* W3 = (const float*)d_in[18];
    const float* b3 = (const float*)d_in[19];
    float* out = (float*)d_out;

    __half *pXPf, *pXPr, *pXv, *pY1s, *pY1, *pH1h, *pY2;
    __half *pW1sh, *pW1vh, *pW2h, *pwfh, *pwrh, *pSh;
    cudaGetSymbolAddress((void**)&pXPf, g_XPf);
    cudaGetSymbolAddress((void**)&pXPr, g_XPr);
    cudaGetSymbolAddress((void**)&pXv,  g_Xv);
    cudaGetSymbolAddress((void**)&pY1s, g_Y1s);
    cudaGetSymbolAddress((void**)&pY1,  g_Y1);
    cudaGetSymbolAddress((void**)&pH1h, g_H1h);
    cudaGetSymbolAddress((void**)&pY2,  g_Y2);
    cudaGetSymbolAddress((void**)&pW1sh, g_W1sh);
    cudaGetSymbolAddress((void**)&pW1vh, g_W1vh);
    cudaGetSymbolAddress((void**)&pW2h, g_W2h);
    cudaGetSymbolAddress((void**)&pwfh, g_wihfh);
    cudaGetSymbolAddress((void**)&pwrh, g_wihrh);
    cudaGetSymbolAddress((void**)&pSh,  g_stateh);

    cudaFuncSetAttribute(lstm_fused, cudaFuncAttributeMaxDynamicSharedMemorySize, LSMEM_TOTAL);
    cudaFuncSetAttribute(hgemm_nt<0>, cudaFuncAttributeMaxDynamicSharedMemorySize, HG_SMEM);
    cudaFuncSetAttribute(hgemm_nt<1>, cudaFuncAttributeMaxDynamicSharedMemorySize, HG_SMEM);
    cudaFuncSetAttribute(hgemm_nt<2>, cudaFuncAttributeMaxDynamicSharedMemorySize, HG_SMEM);

    // 0. weight/state conversions (tiny)
    tohalf_strided<<<(H1*SD + 255)/256, 256>>>(W1, pW1sh, H1, MLPIN, 0,  SD);
    tohalf_strided<<<(H1*XV + 255)/256, 256>>>(W1, pW1vh, H1, MLPIN, SD, XV);
    tohalf<<<(H2*H1 + 255)/256, 256>>>(W2, pW2h, H2*H1);
    tohalf<<<(G4*ED + 255)/256, 256>>>(w_ih_f, pwfh, G4*ED);
    tohalf<<<(G4*ED + 255)/256, 256>>>(w_ih_r, pwrh, G4*ED);
    tohalf<<<(BB*SD + 255)/256, 256>>>(state, pSh, BB*SD);

    // 1. V into Xv
    fill_V<<<(RR*ED + 255)/256, 256>>>(action);

    // 2. attention -> Xv[:,384:512]
    attn_kernel<<<BB, 128>>>(action);

    // 3. x_proj both directions (fp16 out)
    hgemm_nt<0><<<dim3(G4/HBN_, RR/HBM_), 256, HG_SMEM>>>(pXv + 256, XV, pwfh, ED, pXPf, G4, ED, nullptr);
    hgemm_nt<0><<<dim3(G4/HBN_, RR/HBM_), 256, HG_SMEM>>>(pXv + 256, XV, pwrh, ED, pXPr, G4, ED, nullptr);

    // 3b. Y1s = state @ W1s^T (fp16 out)
    hgemm_nt<0><<<dim3(H1/HBN_, BB/HBM_), 256, HG_SMEM>>>(pSh, SD, pW1sh, SD, pY1s, H1, SD, nullptr);

    // 4. fused persistent LSTM (both directions)
    lstm_fused<<<dim3(BB/LROWS, 2), 256, LSMEM_TOTAL>>>(w_hh_f, w_hh_r,
                                                        b_ih_f, b_hh_f, b_ih_r, b_hh_r);

    // 5. MLP layer 1: Y1 = Xv @ W1v^T + broadcast(Y1s); stats in staged epilogue
    hgemm_nt<2><<<dim3(H1/HBN_, RR/HBM_), 256, HG_SMEM>>>(pXv, XV, pW1vh, XV, pY1, H1, XV, pY1s);
    bn_finalize<<<H1/128, 128>>>(H1);
    bn_apply_relu_h<<<2048, 256>>>(pY1, pH1h, g1, be1, H1);

    // 6. MLP layer 2 + staged stats
    hgemm_nt<1><<<dim3(H2/HBN_, RR/HBM_), 256, HG_SMEM>>>(pH1h, H1, pW2h, H1, pY2, H2, H1, nullptr);
    bn_finalize<<<H2/128, 128>>>(H2);

    // 7. final layer with fused layer-2 BN+ReLU
    final_q<<<RR/8, 256>>>(W3, b3, g2, be2, out);

    // 8. regularizer
    {
        RegArgs ra;
        for (int i = 0; i < 18; i++) {
            ra.p[i] = (const float*)d_in[2 + i];
            ra.n[i] = in_sizes[2 + i];
        }
        reg_partial<<<dim3(18, 16), 256>>>(ra);
        reg_final<<<1, 32>>>(out, out_size);
    }
}